// round 14
// baseline (speedup 1.0000x reference)
#include <cuda_runtime.h>

// Problem constants (fixed-shape problem)
#define NB      32
#define NSITES  65536
#define NNGB    13
#define DIM     3
#define NG      48
#define KDIM    (NG * DIM)             // 144
#define NPREP   16
#define TSITES  128                    // sites per transpose tile
#define NTRANS  (NSITES / TSITES)      // 512 transpose blocks
#define NTILE   2048                   // conv tiles (32 sites each)
#define GRID_C  444                    // 3 per SM, all co-resident

// Scratch (device-global: allocation-free rule)
__device__ __align__(16) float g_InT[NSITES * NB];   // 8 MB, site-major transpose
__device__ float    g_Wpart[NPREP][DIM * NNGB];
__device__ unsigned g_ticket;                        // reset by fused_t each launch

__device__ __forceinline__ void cp_async4(unsigned smem_addr, const void* gptr) {
    asm volatile("cp.async.ca.shared.global [%0], [%1], 4;"
                 :: "r"(smem_addr), "l"(gptr));
}
__device__ __forceinline__ void cp_async_commit() {
    asm volatile("cp.async.commit_group;");
}
__device__ __forceinline__ void cp_async_wait_all() {
    asm volatile("cp.async.wait_group 0;");
}

// ---------------------------------------------------------------------------
// Kernel T: fused transpose + Wmean partials (r13-proven). Also resets the
// conv ticket counter (stream order => safe, replay-safe).
// ---------------------------------------------------------------------------
#define T_SMEM_BYTES (32 * 129 * 4)    // 16512 >= prep's 7648

__global__ __launch_bounds__(256)
void fused_t_kernel(const float* __restrict__ In,
                    const float* __restrict__ wtVC,
                    const float* __restrict__ gdiags,
                    const int*   __restrict__ GnnPerms) {
    __shared__ __align__(16) unsigned char s_raw[T_SMEM_BYTES];
    int tid = threadIdx.x;

    if (blockIdx.x == 0 && tid == 0) g_ticket = 0;   // reset for conv

    if (blockIdx.x < NTRANS) {
        float* tile = (float*)s_raw;               // [32][129] padded
        int s0 = blockIdx.x * TSITES;
        #pragma unroll
        for (int k = 0; k < 16; k++) {
            int i = tid + (k << 8);
            int b = i >> 7, x = i & 127;
            tile[b * 129 + x] = In[b * NSITES + s0 + x];
        }
        __syncthreads();
        #pragma unroll
        for (int k = 0; k < 16; k++) {
            int i  = tid + (k << 8);
            int sl = i >> 5, b = i & 31;
            g_InT[(s0 + sl) * NB + b] = tile[b * 129 + sl];
        }
    } else {
        int p = blockIdx.x - NTRANS;
        float* B  = (float*)s_raw;                 // [144][13]
        float* sW = (float*)(s_raw + 7488);        // 39 accumulators
        if (tid < DIM * NNGB) sW[tid] = 0.f;
        for (int i = tid; i < KDIM * NNGB; i += 256) {
            int k = i / NNGB, j = i % NNGB;
            B[i] = wtVC[(k % 3) * NNGB + GnnPerms[(k / 3) * NNGB + j]];
        }
        __syncthreads();
        int w = tid >> 5, lane = tid & 31;
        for (int rl = w; rl < 9; rl += 8) {
            int r = p * 9 + rl;
            float acc[NNGB];
            #pragma unroll
            for (int j = 0; j < NNGB; j++) acc[j] = 0.f;
            for (int k = lane; k < KDIM; k += 32) {
                float gv = gdiags[r * KDIM + k];
                #pragma unroll
                for (int j = 0; j < NNGB; j++) acc[j] += gv * B[k * NNGB + j];
            }
            #pragma unroll
            for (int j = 0; j < NNGB; j++) {
                #pragma unroll
                for (int o = 16; o > 0; o >>= 1)
                    acc[j] += __shfl_xor_sync(0xffffffffu, acc[j], o);
            }
            if (lane == 0) {
                int d = r % 3;
                #pragma unroll
                for (int j = 0; j < NNGB; j++)
                    atomicAdd(&sW[d * NNGB + j], acc[j]);
            }
        }
        __syncthreads();
        if (tid < DIM * NNGB) g_Wpart[p][tid] = sW[tid];
    }
}

// ---------------------------------------------------------------------------
// Kernel C: ticketed, cross-tile-pipelined gather + contraction.
// 444 co-resident blocks; each loops over 32-site tiles from an atomic
// ticket. Double-buffered sidx; NEXT tile's indices prefetched via cp.async
// (no register cost) while the CURRENT tile's 13 batched LDG.128 gathers
// and FMAs execute. Gather core + STG.128 epilogue = r9/r13 verbatim.
// ---------------------------------------------------------------------------
__global__ __launch_bounds__(256, 3)
void conv_kernel(const int* __restrict__ NNsites, float* __restrict__ out) {
    __shared__ float    Wm[40];
    __shared__ int      sidx[2][NNGB * 32];
    __shared__ float    sout[DIM * 1064];   // d*1064 + b*33 + si
    __shared__ unsigned s_tk;

    int tid = threadIdx.x;

    if (tid < DIM * NNGB) {
        float s = 0.f;
        #pragma unroll
        for (int p = 0; p < NPREP; p++) s += g_Wpart[p][tid];
        Wm[tid] = s * (1.0f / (float)NG);
    }

    // -- prologue: first ticket + plain sidx load --------------------------
    if (tid == 0) s_tk = atomicAdd(&g_ticket, 1);
    __syncthreads();                              // (A) s_tk visible
    unsigned t = s_tk;
    if (t < NTILE) {
        for (int i = tid; i < NNGB * 32; i += 256) {
            int j = i >> 5, si = i & 31;
            sidx[0][i] = NNsites[j * NSITES + t * 32 + si];
        }
    }
    if (tid == 0) s_tk = atomicAdd(&g_ticket, 1); // next ticket (race-free:
    __syncthreads();                              //  (B) after all read t)

    int w    = tid >> 5;
    int l    = tid & 31;
    int site = (w << 2) + (l >> 3);   // 0..31
    int c    = l & 7;                 // 16B chunk -> batches 4c..4c+3
    const float4* __restrict__ InT4 = (const float4*)g_InT;

    int cur = 0;
    while (t < NTILE) {
        unsigned tn = s_tk;           // stable since barrier (B)/(E)
        int s0 = t * 32;

        // 1) current tile: read indices, issue all 13 gathers back-to-back
        int idx[NNGB];
        #pragma unroll
        for (int j = 0; j < NNGB; j++) idx[j] = sidx[cur][j * 32 + site];

        float4 v[NNGB];
        #pragma unroll
        for (int j = 0; j < NNGB; j++) v[j] = __ldg(&InT4[idx[j] * 8 + c]);

        // 2) prefetch next tile's indices into the other buffer (cp.async:
        //    zero register cost, completion enforced at barrier (E))
        if (tn < NTILE) {
            for (int i = tid; i < NNGB * 32; i += 256) {
                int j = i >> 5, si = i & 31;
                cp_async4((unsigned)__cvta_generic_to_shared(&sidx[cur ^ 1][i]),
                          &NNsites[j * NSITES + tn * 32 + si]);
            }
        }
        cp_async_commit();

        // 3) contraction
        float4 a0 = make_float4(0.f, 0.f, 0.f, 0.f);
        float4 a1 = a0, a2 = a0;
        #pragma unroll
        for (int j = 0; j < NNGB; j++) {
            float w0 = Wm[j], w1 = Wm[NNGB + j], w2 = Wm[2 * NNGB + j];
            a0.x += w0 * v[j].x; a0.y += w0 * v[j].y; a0.z += w0 * v[j].z; a0.w += w0 * v[j].w;
            a1.x += w1 * v[j].x; a1.y += w1 * v[j].y; a1.z += w1 * v[j].z; a1.w += w1 * v[j].w;
            a2.x += w2 * v[j].x; a2.y += w2 * v[j].y; a2.z += w2 * v[j].z; a2.w += w2 * v[j].w;
        }

        // 4) epilogue: stage (conflict-free), then 3 STG.128 per thread
        int b0 = c << 2;
        sout[0 * 1064 + (b0 + 0) * 33 + site] = a0.x;
        sout[0 * 1064 + (b0 + 1) * 33 + site] = a0.y;
        sout[0 * 1064 + (b0 + 2) * 33 + site] = a0.z;
        sout[0 * 1064 + (b0 + 3) * 33 + site] = a0.w;
        sout[1 * 1064 + (b0 + 0) * 33 + site] = a1.x;
        sout[1 * 1064 + (b0 + 1) * 33 + site] = a1.y;
        sout[1 * 1064 + (b0 + 2) * 33 + site] = a1.z;
        sout[1 * 1064 + (b0 + 3) * 33 + site] = a1.w;
        sout[2 * 1064 + (b0 + 0) * 33 + site] = a2.x;
        sout[2 * 1064 + (b0 + 1) * 33 + site] = a2.y;
        sout[2 * 1064 + (b0 + 2) * 33 + site] = a2.z;
        sout[2 * 1064 + (b0 + 3) * 33 + site] = a2.w;
        __syncthreads();                          // (D)

        #pragma unroll
        for (int k = 0; k < 3; k++) {
            int f4  = tid + (k << 8);
            int p   = f4 & 7;
            int row = f4 >> 3;        // b*3+d
            int d   = row % 3;
            int b   = row / 3;
            int si  = p << 2;
            float4 o;
            o.x = sout[d * 1064 + b * 33 + si];
            o.y = sout[d * 1064 + b * 33 + si + 1];
            o.z = sout[d * 1064 + b * 33 + si + 2];
            o.w = sout[d * 1064 + b * 33 + si + 3];
            ((float4*)(out + row * NSITES + s0))[p] = o;
        }

        // 5) advance pipeline: next-next ticket, wait prefetch, publish
        if (tid == 0 && tn < NTILE) s_tk = atomicAdd(&g_ticket, 1); // after (D):
        cp_async_wait_all();                      //  all threads read s_tk already
        __syncthreads();                          // (E) sidx[cur^1] + s_tk visible
        cur ^= 1;
        t = tn;
    }
}

// ---------------------------------------------------------------------------
// Launch: In, wtVC, gdiags, GnnPerms, NNsites (metadata order). TWO kernels.
// ---------------------------------------------------------------------------
extern "C" void kernel_launch(void* const* d_in, const int* in_sizes, int n_in,
                              void* d_out, int out_size) {
    const float* In       = (const float*)d_in[0];
    const float* wtVC     = (const float*)d_in[1];
    const float* gdiags   = (const float*)d_in[2];
    const int*   GnnPerms = (const int*)  d_in[3];
    const int*   NNsites  = (const int*)  d_in[4];
    float*       out      = (float*)d_out;

    fused_t_kernel<<<NTRANS + NPREP, 256>>>(In, wtVC, gdiags, GnnPerms);

    conv_kernel<<<GRID_C, 256>>>(NNsites, out);
}